// round 7
// baseline (speedup 1.0000x reference)
#include <cuda_runtime.h>
#include <cuda_bf16.h>
#include <cstddef>

// Problem constants
#define SQ    2048      // sequence length
#define HIDD  2048      // hidden
#define NHQ   16        // query heads
#define NKVH  4         // kv heads
#define HDIM  128       // head dim
#define QKVN  3072      // (16 + 2*4) * 128
#define GRP   4         // NHQ / NKVH
#define QSCALE 0.08838834764831845f   // 128^-0.5
#define RMSEPS 1e-6f

// ---------------------------------------------------------------------------
// Scratch (static device globals; allocation is forbidden)
// ---------------------------------------------------------------------------
__device__ float g_qkv   [(size_t)SQ * QKVN];            // 25 MB
__device__ float g_q     [(size_t)SQ * NHQ * HDIM];      // 16 MB  (normed, roped, scaled)
__device__ float g_k     [(size_t)SQ * NKVH * HDIM];     // 4 MB
__device__ float g_v     [(size_t)SQ * NKVH * HDIM];     // 4 MB
__device__ float g_scores[(size_t)NHQ * SQ * SQ];        // 256 MB (scores -> probs in place)
__device__ float g_attn  [(size_t)SQ * NHQ * HDIM];      // 16 MB  ([s, h*128+d])

// ---------------------------------------------------------------------------
// 128x128x8 SGEMM core: C = A * B^T (+bias), A:[M,K] lda, B:[N,K] ldb
// 256 threads, each computes 8x8.
// ---------------------------------------------------------------------------
#define BM 128
#define BN 128
#define BKK 8

__device__ __forceinline__ void sgemm_tile_abt(
    const float* __restrict__ A, int lda,
    const float* __restrict__ B, int ldb,
    float* __restrict__ C, int ldc,
    int K, const float* __restrict__ bias, int bx, int by)
{
    __shared__ float As[BKK][BM];
    __shared__ float Bs[BKK][BN];

    const int tid  = threadIdx.x;
    const int lrow = tid >> 1;          // 0..127
    const int lcol = (tid & 1) * 4;     // 0 or 4
    const int tx   = tid & 15;
    const int ty   = tid >> 4;

    const float* Ab = A + (size_t)by * BM * lda;
    const float* Bb = B + (size_t)bx * BN * ldb;

    float acc[8][8];
#pragma unroll
    for (int i = 0; i < 8; i++)
#pragma unroll
        for (int j = 0; j < 8; j++) acc[i][j] = 0.f;

    for (int k0 = 0; k0 < K; k0 += BKK) {
        float4 av = *reinterpret_cast<const float4*>(Ab + (size_t)lrow * lda + k0 + lcol);
        float4 bv = *reinterpret_cast<const float4*>(Bb + (size_t)lrow * ldb + k0 + lcol);
        As[lcol + 0][lrow] = av.x; As[lcol + 1][lrow] = av.y;
        As[lcol + 2][lrow] = av.z; As[lcol + 3][lrow] = av.w;
        Bs[lcol + 0][lrow] = bv.x; Bs[lcol + 1][lrow] = bv.y;
        Bs[lcol + 2][lrow] = bv.z; Bs[lcol + 3][lrow] = bv.w;
        __syncthreads();
#pragma unroll
        for (int k = 0; k < BKK; k++) {
            float4 a0 = *reinterpret_cast<const float4*>(&As[k][ty * 8]);
            float4 a1 = *reinterpret_cast<const float4*>(&As[k][ty * 8 + 4]);
            float4 b0 = *reinterpret_cast<const float4*>(&Bs[k][tx * 8]);
            float4 b1 = *reinterpret_cast<const float4*>(&Bs[k][tx * 8 + 4]);
            float ar[8] = {a0.x, a0.y, a0.z, a0.w, a1.x, a1.y, a1.z, a1.w};
            float br[8] = {b0.x, b0.y, b0.z, b0.w, b1.x, b1.y, b1.z, b1.w};
#pragma unroll
            for (int i = 0; i < 8; i++)
#pragma unroll
                for (int j = 0; j < 8; j++)
                    acc[i][j] = fmaf(ar[i], br[j], acc[i][j]);
        }
        __syncthreads();
    }

#pragma unroll
    for (int i = 0; i < 8; i++) {
        int row = by * BM + ty * 8 + i;
#pragma unroll
        for (int j = 0; j < 8; j += 4) {
            int col = bx * BN + tx * 8 + j;
            float4 v;
            v.x = acc[i][j];     v.y = acc[i][j + 1];
            v.z = acc[i][j + 2]; v.w = acc[i][j + 3];
            if (bias) {
                v.x += bias[col];     v.y += bias[col + 1];
                v.z += bias[col + 2]; v.w += bias[col + 3];
            }
            *reinterpret_cast<float4*>(C + (size_t)row * ldc + col) = v;
        }
    }
}

// ---------------------------------------------------------------------------
// GEMM wrappers
// ---------------------------------------------------------------------------
__global__ void __launch_bounds__(256) k_qkv_gemm(
    const float* __restrict__ hidden, const float* __restrict__ wqkv,
    const float* __restrict__ bqkv)
{
    sgemm_tile_abt(hidden, HIDD, wqkv, HIDD, g_qkv, QKVN, HIDD, bqkv,
                   blockIdx.x, blockIdx.y);
}

__global__ void __launch_bounds__(256) k_scores_gemm()
{
    const int bx = blockIdx.x, by = blockIdx.y, h = blockIdx.z;
    if (bx > by) return;  // tile entirely above causal diagonal: never read
    const float* A = g_q + (size_t)h * HDIM;            // [S, 128], lda = 2048
    const float* B = g_k + (size_t)(h >> 2) * HDIM;     // [S, 128], ldb = 512
    float* C = g_scores + (size_t)h * SQ * SQ;          // [S, S]
    sgemm_tile_abt(A, NHQ * HDIM, B, NKVH * HDIM, C, SQ, HDIM, nullptr, bx, by);
}

__global__ void __launch_bounds__(256) k_out_gemm(
    const float* __restrict__ wo, const float* __restrict__ bo,
    float* __restrict__ out)
{
    sgemm_tile_abt(g_attn, NHQ * HDIM, wo, HIDD, out, HIDD, HIDD, bo,
                   blockIdx.x, blockIdx.y);
}

// ---------------------------------------------------------------------------
// PV: out[s,d] = sum_t p[s,t] * v[t,d]   (A*B form, N=128, K limited by causal)
// ---------------------------------------------------------------------------
__global__ void __launch_bounds__(256) k_pv_gemm()
{
    const int by = blockIdx.y, h = blockIdx.z;
    const float* A = g_scores + (size_t)h * SQ * SQ;    // probs, lda = S
    const float* B = g_v + (size_t)(h >> 2) * HDIM;     // [t, 128], ldb = 512
    float* C = g_attn + (size_t)h * HDIM;               // ldc = 2048

    __shared__ float As[BKK][BM];
    __shared__ float Bs[BKK][BN];

    const int tid  = threadIdx.x;
    const int lrow = tid >> 1;
    const int lcol = (tid & 1) * 4;
    const int brow = tid >> 5;          // 0..7
    const int bcol = (tid & 31) * 4;    // 0..124
    const int tx   = tid & 15;
    const int ty   = tid >> 4;

    float acc[8][8];
#pragma unroll
    for (int i = 0; i < 8; i++)
#pragma unroll
        for (int j = 0; j < 8; j++) acc[i][j] = 0.f;

    int kmax = (by + 1) * BM;           // p[s,t]=0 for t>s
    if (kmax > SQ) kmax = SQ;

    for (int k0 = 0; k0 < kmax; k0 += BKK) {
        float4 av = *reinterpret_cast<const float4*>(
            A + (size_t)(by * BM + lrow) * SQ + k0 + lcol);
        As[lcol + 0][lrow] = av.x; As[lcol + 1][lrow] = av.y;
        As[lcol + 2][lrow] = av.z; As[lcol + 3][lrow] = av.w;
        float4 bv = *reinterpret_cast<const float4*>(
            B + (size_t)(k0 + brow) * (NKVH * HDIM) + bcol);
        *reinterpret_cast<float4*>(&Bs[brow][bcol]) = bv;
        __syncthreads();
#pragma unroll
        for (int k = 0; k < BKK; k++) {
            float4 a0 = *reinterpret_cast<const float4*>(&As[k][ty * 8]);
            float4 a1 = *reinterpret_cast<const float4*>(&As[k][ty * 8 + 4]);
            float4 b0 = *reinterpret_cast<const float4*>(&Bs[k][tx * 8]);
            float4 b1 = *reinterpret_cast<const float4*>(&Bs[k][tx * 8 + 4]);
            float ar[8] = {a0.x, a0.y, a0.z, a0.w, a1.x, a1.y, a1.z, a1.w};
            float br[8] = {b0.x, b0.y, b0.z, b0.w, b1.x, b1.y, b1.z, b1.w};
#pragma unroll
            for (int i = 0; i < 8; i++)
#pragma unroll
                for (int j = 0; j < 8; j++)
                    acc[i][j] = fmaf(ar[i], br[j], acc[i][j]);
        }
        __syncthreads();
    }

#pragma unroll
    for (int i = 0; i < 8; i++) {
        int row = by * BM + ty * 8 + i;
#pragma unroll
        for (int j = 0; j < 8; j += 4) {
            int col = tx * 8 + j;
            float4 v;
            v.x = acc[i][j];     v.y = acc[i][j + 1];
            v.z = acc[i][j + 2]; v.w = acc[i][j + 3];
            *reinterpret_cast<float4*>(C + (size_t)row * (NHQ * HDIM) + col) = v;
        }
    }
}

// ---------------------------------------------------------------------------
// RMSNorm + RoPE (+ q scaling). grid (S, 24), 128 threads.
//   y in [0,16): q head;  [16,20): k head;  [20,24): v head (copy only)
// ---------------------------------------------------------------------------
__global__ void __launch_bounds__(128) k_norm_rope(
    const float* __restrict__ cosb, const float* __restrict__ sinb,
    const float* __restrict__ qw,   const float* __restrict__ kw)
{
    const int s  = blockIdx.x;
    const int hh = blockIdx.y;
    const int d  = threadIdx.x;
    const float* row = g_qkv + (size_t)s * QKVN;

    if (hh >= 20) {  // v: passthrough
        int kv = hh - 20;
        g_v[(size_t)s * (NKVH * HDIM) + kv * HDIM + d] =
            row[NHQ * HDIM + NKVH * HDIM + kv * HDIM + d];
        return;
    }

    const bool isq = (hh < 16);
    const int off = isq ? hh * HDIM : NHQ * HDIM + (hh - 16) * HDIM;
    float x = row[off + d];

    // mean of squares over 128
    float sq = x * x;
#pragma unroll
    for (int o = 16; o; o >>= 1) sq += __shfl_xor_sync(0xffffffffu, sq, o);
    __shared__ float ws[4];
    __shared__ float rinv;
    if ((d & 31) == 0) ws[d >> 5] = sq;
    __syncthreads();
    if (d == 0)
        rinv = rsqrtf((ws[0] + ws[1] + ws[2] + ws[3]) * (1.0f / 128.0f) + RMSEPS);
    __syncthreads();

    const float w = isq ? qw[d] : kw[d];
    float xn = x * rinv * w;

    __shared__ float xs[128];
    xs[d] = xn;
    __syncthreads();

    const int j = d & 63;
    const float c  = cosb[(size_t)s * 64 + j];
    const float sn = sinb[(size_t)s * 64 + j];
    float o;
    if (d < 64) o = xs[d] * c - xs[d + 64] * sn;
    else        o = xs[j] * sn + xs[j + 64] * c;

    if (isq)
        g_q[(size_t)s * (NHQ * HDIM) + hh * HDIM + d] = o * QSCALE;
    else
        g_k[(size_t)s * (NKVH * HDIM) + (hh - 16) * HDIM + d] = o;
}

// ---------------------------------------------------------------------------
// Causal softmax, in place in g_scores. grid (S, NH), 256 threads.
// Reads only t<=s; writes p[t]=0 for t>s (so PV is a plain GEMM).
// ---------------------------------------------------------------------------
__global__ void __launch_bounds__(256) k_softmax()
{
    const int s = blockIdx.x, h = blockIdx.y;
    float* row = g_scores + ((size_t)h * SQ + s) * SQ;
    const int n = s + 1;
    const int tid = threadIdx.x;

    __shared__ float r1[8], r2[8];

    float m = -3.4e38f;
    for (int t = tid; t < n; t += 256) m = fmaxf(m, row[t]);
#pragma unroll
    for (int o = 16; o; o >>= 1) m = fmaxf(m, __shfl_xor_sync(0xffffffffu, m, o));
    if ((tid & 31) == 0) r1[tid >> 5] = m;
    __syncthreads();
    m = r1[0];
#pragma unroll
    for (int i = 1; i < 8; i++) m = fmaxf(m, r1[i]);

    float sum = 0.f;
    for (int t = tid; t < n; t += 256) {
        float e = expf(row[t] - m);
        row[t] = e;
        sum += e;
    }
#pragma unroll
    for (int o = 16; o; o >>= 1) sum += __shfl_xor_sync(0xffffffffu, sum, o);
    if ((tid & 31) == 0) r2[tid >> 5] = sum;
    __syncthreads();
    sum = 0.f;
#pragma unroll
    for (int i = 0; i < 8; i++) sum += r2[i];
    const float inv = 1.0f / sum;

    for (int t = tid; t < SQ; t += 256)
        row[t] = (t < n) ? row[t] * inv : 0.f;
}

// ---------------------------------------------------------------------------
// Launch
// Inputs (metadata order):
//  0 hidden_states [1,2048,2048] f32   1 cos [2048,64]   2 sin [2048,64]
//  3 k_cache       4 v_cache           5 mask
//  6 wqkv [3072,2048]  7 bqkv [3072]   8 wo [2048,2048]  9 bo [2048]
// 10 q_norm_w [128]  11 k_norm_w [128] 12 kv_write_indices [2048] i32
// ---------------------------------------------------------------------------
extern "C" void kernel_launch(void* const* d_in, const int* in_sizes, int n_in,
                              void* d_out, int out_size)
{
    const float* hidden = (const float*)d_in[0];
    const float* cosb   = (const float*)d_in[1];
    const float* sinb   = (const float*)d_in[2];
    const float* wqkv   = (const float*)d_in[6];
    const float* bqkv   = (const float*)d_in[7];
    const float* wo     = (const float*)d_in[8];
    const float* bo     = (const float*)d_in[9];
    const float* qw     = (const float*)d_in[10];
    const float* kw     = (const float*)d_in[11];
    float* out = (float*)d_out;

    // 1) QKV projection: [2048,2048] x [3072,2048]^T -> [2048,3072]
    k_qkv_gemm<<<dim3(QKVN / BN, SQ / BM), 256>>>(hidden, wqkv, bqkv);

    // 2) RMSNorm + RoPE + scale; split into q/k/v scratch
    k_norm_rope<<<dim3(SQ, NHQ + 2 * NKVH), 128>>>(cosb, sinb, qw, kw);

    // 3) Scores per head (causal tile skip)
    k_scores_gemm<<<dim3(SQ / BN, SQ / BM, NHQ), 256>>>();

    // 4) Causal softmax (in place)
    k_softmax<<<dim3(SQ, NHQ), 256>>>();

    // 5) P @ V per head (K-limited by causal zero structure)
    k_pv_gemm<<<dim3(1, SQ / BM, NHQ), 256>>>();

    // 6) Output projection: [2048,2048] x [2048,2048]^T + bo
    k_out_gemm<<<dim3(HIDD / BN, SQ / BM), 256>>>(wo, bo, out);

    (void)in_sizes; (void)n_in; (void)out_size;
}

// round 8
// speedup vs baseline: 2.1233x; 2.1233x over previous
#include <cuda_runtime.h>
#include <cstddef>
#include <cstdint>

#define SQ    2048
#define HIDD  2048
#define NHQ   16
#define NKVH  4
#define HDIM  128
#define QKVN  3072
#define QSCALE 0.08838834764831845f
#define RMSEPS 1e-6f

// ---------------------------------------------------------------------------
// Scratch (static device globals; allocation is forbidden)
// ---------------------------------------------------------------------------
__device__ float g_qkv   [(size_t)SQ * QKVN];
__device__ float g_q     [(size_t)SQ * NHQ * HDIM];     // tf32-rounded
__device__ float g_k     [(size_t)SQ * NKVH * HDIM];    // tf32-rounded
__device__ float g_vT    [(size_t)NKVH * HDIM * SQ];    // V^T, tf32-rounded
__device__ float g_scores[(size_t)NHQ * SQ * SQ];       // scores -> probs (tf32)
__device__ float g_attn  [(size_t)SQ * NHQ * HDIM];     // tf32-rounded
__device__ float g_hhi   [(size_t)SQ * HIDD];           // hidden hi/lo split
__device__ float g_hlo   [(size_t)SQ * HIDD];
__device__ float g_whi   [(size_t)QKVN * HIDD];         // wqkv hi/lo split
__device__ float g_wlo   [(size_t)QKVN * HIDD];
__device__ float g_wot   [(size_t)HIDD * HIDD];         // wo tf32-rounded

// ---------------------------------------------------------------------------
// Helpers
// ---------------------------------------------------------------------------
__device__ __forceinline__ float tf32r(float x) {
    unsigned u;
    asm("cvt.rna.tf32.f32 %0, %1;" : "=r"(u) : "f"(x));
    return __uint_as_float(u);
}

__device__ __forceinline__ void cp16(uint32_t dst, const float* src) {
    asm volatile("cp.async.cg.shared.global [%0], [%1], 16;\n" :: "r"(dst), "l"(src));
}

__device__ __forceinline__ void ldm4(uint32_t* r, uint32_t addr) {
    asm volatile("ldmatrix.sync.aligned.m8n8.x4.shared.b16 {%0,%1,%2,%3}, [%4];\n"
                 : "=r"(r[0]), "=r"(r[1]), "=r"(r[2]), "=r"(r[3]) : "r"(addr));
}

__device__ __forceinline__ void mma8(float* c, const uint32_t* a,
                                     uint32_t b0, uint32_t b1) {
    asm volatile(
        "mma.sync.aligned.m16n8k8.row.col.f32.tf32.tf32.f32 "
        "{%0,%1,%2,%3}, {%4,%5,%6,%7}, {%8,%9}, {%0,%1,%2,%3};\n"
        : "+f"(c[0]), "+f"(c[1]), "+f"(c[2]), "+f"(c[3])
        : "r"(a[0]), "r"(a[1]), "r"(a[2]), "r"(a[3]), "r"(b0), "r"(b1));
}

// ---------------------------------------------------------------------------
// tf32 GEMM core: C = A * B^T (+bias)(+=C)(tf32-round out), tiles 128x128x32.
// A:[M,K] lda, B:[N,K] ldb, all dims multiples of tile. 256 threads, 8 warps,
// warp tile 64x32. cp.async double-buffered, ldmatrix fragments, padded smem.
// ---------------------------------------------------------------------------
#define SST   36                       // smem row stride (floats)
#define STAGE (128 * SST)              // floats per matrix per stage
#define GSMEM (2 * 2 * STAGE * 4)      // bytes: 2 stages x (A+B) = 73728

__device__ __forceinline__ void cp_stage(const float* Ag, const float* Bg,
                                         int lda, int ldb,
                                         uint32_t dA, uint32_t dB) {
#pragma unroll
    for (int i = 0; i < 4; i++) {
        cp16(dA + i * 32 * SST * 4, Ag + (size_t)(i * 32) * lda);
        cp16(dB + i * 32 * SST * 4, Bg + (size_t)(i * 32) * ldb);
    }
}

__device__ __forceinline__ void gemm_core(
    const float* __restrict__ A, int lda,
    const float* __restrict__ B, int ldb,
    float* __restrict__ C, int ldc,
    int K, const float* __restrict__ bias,
    int accum, int cvt, int bx, int by)
{
    extern __shared__ float dsm[];
    const int tid  = threadIdx.x;
    const int wid  = tid >> 5, lane = tid & 31;
    const int wm   = (wid & 1) * 64, wn = (wid >> 1) * 32;
    const int ldrw = tid >> 3, ldcl = (tid & 7) * 4;

    const uint32_t sb = (uint32_t)__cvta_generic_to_shared(dsm);
    const float* Ag = A + (size_t)(by * 128 + ldrw) * lda + ldcl;
    const float* Bg = B + (size_t)(bx * 128 + ldrw) * ldb + ldcl;
    const uint32_t dA0 = sb + (ldrw * SST + ldcl) * 4;
    const uint32_t dB0 = dA0 + STAGE * 4;

    const int nK = K >> 5;

    float acc[4][4][4];
#pragma unroll
    for (int a = 0; a < 4; a++)
#pragma unroll
        for (int b = 0; b < 4; b++)
#pragma unroll
            for (int c = 0; c < 4; c++) acc[a][b][c] = 0.f;

    const int mi  = lane >> 3, l7 = lane & 7;
    const int aro = (mi & 1) * 8 + l7, aco = (mi >> 1) * 4;
    const int bro = (mi >> 1) * 8 + l7, bco = (mi & 1) * 4;

    cp_stage(Ag, Bg, lda, ldb, dA0, dB0);
    asm volatile("cp.async.commit_group;\n");

    for (int kt = 0; kt < nK; kt++) {
        if (kt + 1 < nK) {
            int st = (kt + 1) & 1;
            cp_stage(Ag + (kt + 1) * 32, Bg + (kt + 1) * 32, lda, ldb,
                     dA0 + st * (2 * STAGE * 4), dB0 + st * (2 * STAGE * 4));
            asm volatile("cp.async.commit_group;\n");
            asm volatile("cp.async.wait_group 1;\n");
        } else {
            asm volatile("cp.async.wait_group 0;\n");
        }
        __syncthreads();

        const uint32_t sA = sb + (kt & 1) * (2 * STAGE * 4);
        const uint32_t sB = sA + STAGE * 4;
#pragma unroll
        for (int k = 0; k < 32; k += 8) {
            uint32_t bq[8];
            ldm4(bq,     sB + ((wn +      bro) * SST + k + bco) * 4);
            ldm4(bq + 4, sB + ((wn + 16 + bro) * SST + k + bco) * 4);
#pragma unroll
            for (int mt = 0; mt < 4; mt++) {
                uint32_t aq[4];
                ldm4(aq, sA + ((wm + 16 * mt + aro) * SST + k + aco) * 4);
                mma8(acc[mt][0], aq, bq[0], bq[1]);
                mma8(acc[mt][1], aq, bq[2], bq[3]);
                mma8(acc[mt][2], aq, bq[4], bq[5]);
                mma8(acc[mt][3], aq, bq[6], bq[7]);
            }
        }
        __syncthreads();
    }

    // Epilogue
    const int g = lane >> 2, tg = lane & 3;
#pragma unroll
    for (int mt = 0; mt < 4; mt++) {
#pragma unroll
        for (int nt = 0; nt < 4; nt++) {
            const int r0 = by * 128 + wm + 16 * mt + g;
            const int c0 = bx * 128 + wn + 8 * nt + tg * 2;
            float x0 = acc[mt][nt][0], x1 = acc[mt][nt][1];
            float x2 = acc[mt][nt][2], x3 = acc[mt][nt][3];
            if (bias) {
                float b0 = bias[c0], b1 = bias[c0 + 1];
                x0 += b0; x1 += b1; x2 += b0; x3 += b1;
            }
            float2* p0 = reinterpret_cast<float2*>(C + (size_t)r0 * ldc + c0);
            float2* p1 = reinterpret_cast<float2*>(C + (size_t)(r0 + 8) * ldc + c0);
            if (accum) {
                float2 o0 = *p0, o1 = *p1;
                x0 += o0.x; x1 += o0.y; x2 += o1.x; x3 += o1.y;
            }
            if (cvt) { x0 = tf32r(x0); x1 = tf32r(x1); x2 = tf32r(x2); x3 = tf32r(x3); }
            *p0 = make_float2(x0, x1);
            *p1 = make_float2(x2, x3);
        }
    }
}

// ---------------------------------------------------------------------------
// GEMM kernels
// ---------------------------------------------------------------------------
__global__ void __launch_bounds__(256, 2) k_qkv1(const float* __restrict__ bias) {
    gemm_core(g_hhi, HIDD, g_whi, HIDD, g_qkv, QKVN, HIDD, bias, 0, 0,
              blockIdx.x, blockIdx.y);
}
__global__ void __launch_bounds__(256, 2) k_qkv2() {
    gemm_core(g_hhi, HIDD, g_wlo, HIDD, g_qkv, QKVN, HIDD, nullptr, 1, 0,
              blockIdx.x, blockIdx.y);
}
__global__ void __launch_bounds__(256, 2) k_qkv3() {
    gemm_core(g_hlo, HIDD, g_whi, HIDD, g_qkv, QKVN, HIDD, nullptr, 1, 0,
              blockIdx.x, blockIdx.y);
}
__global__ void __launch_bounds__(256, 2) k_scores() {
    const int bx = blockIdx.x, by = blockIdx.y, h = blockIdx.z;
    if (bx > by) return;  // entirely above causal diagonal
    gemm_core(g_q + h * HDIM, NHQ * HDIM,
              g_k + (h >> 2) * HDIM, NKVH * HDIM,
              g_scores + (size_t)h * SQ * SQ, SQ, HDIM, nullptr, 0, 0, bx, by);
}
__global__ void __launch_bounds__(256, 2) k_pv() {
    const int by = blockIdx.y, h = blockIdx.z;
    const int kmax = (by + 1) * 128;  // p[s,t]=0 for t>s
    gemm_core(g_scores + (size_t)h * SQ * SQ, SQ,
              g_vT + (size_t)(h >> 2) * HDIM * SQ, SQ,
              g_attn + h * HDIM, NHQ * HDIM, kmax, nullptr, 0, 1, 0, by);
}
__global__ void __launch_bounds__(256, 2) k_out(const float* __restrict__ bo,
                                                float* __restrict__ out) {
    gemm_core(g_attn, NHQ * HDIM, g_wot, HIDD, out, HIDD, HIDD, bo, 0, 0,
              blockIdx.x, blockIdx.y);
}

// ---------------------------------------------------------------------------
// tf32 prep kernels
// ---------------------------------------------------------------------------
__global__ void __launch_bounds__(256) k_split_h(const float* __restrict__ x) {
    int i = blockIdx.x * 256 + threadIdx.x;
    if (i < SQ * HIDD) {
        float v = x[i], h = tf32r(v);
        g_hhi[i] = h; g_hlo[i] = tf32r(v - h);
    }
}
__global__ void __launch_bounds__(256) k_split_w(const float* __restrict__ x) {
    int i = blockIdx.x * 256 + threadIdx.x;
    if (i < QKVN * HIDD) {
        float v = x[i], h = tf32r(v);
        g_whi[i] = h; g_wlo[i] = tf32r(v - h);
    }
}
__global__ void __launch_bounds__(256) k_cvt_wo(const float* __restrict__ x) {
    int i = blockIdx.x * 256 + threadIdx.x;
    if (i < HIDD * HIDD) g_wot[i] = tf32r(x[i]);
}

// V transpose: g_vT[c][s] = tf32(g_qkv[s][2560 + c]),  c in [0, 512)
__global__ void __launch_bounds__(256) k_vT() {
    __shared__ float t[32][33];
    const int c0 = blockIdx.x * 32, s0 = blockIdx.y * 32;
    const int tx = threadIdx.x, ty = threadIdx.y;  // 32 x 8
#pragma unroll
    for (int j = 0; j < 32; j += 8)
        t[ty + j][tx] = g_qkv[(size_t)(s0 + ty + j) * QKVN
                              + (NHQ + NKVH) * HDIM + c0 + tx];
    __syncthreads();
#pragma unroll
    for (int j = 0; j < 32; j += 8)
        g_vT[(size_t)(c0 + ty + j) * SQ + s0 + tx] = tf32r(t[tx][ty + j]);
}

// ---------------------------------------------------------------------------
// RMSNorm + RoPE (+q scaling), outputs tf32-rounded. grid (S, 20), 128 thr.
// ---------------------------------------------------------------------------
__global__ void __launch_bounds__(128) k_norm_rope(
    const float* __restrict__ cosb, const float* __restrict__ sinb,
    const float* __restrict__ qw,   const float* __restrict__ kw)
{
    const int s  = blockIdx.x;
    const int hh = blockIdx.y;       // [0,16): q head; [16,20): k head
    const int d  = threadIdx.x;
    const float* row = g_qkv + (size_t)s * QKVN;

    const bool isq = (hh < 16);
    const int off = isq ? hh * HDIM : NHQ * HDIM + (hh - 16) * HDIM;
    float x = row[off + d];

    float sq = x * x;
#pragma unroll
    for (int o = 16; o; o >>= 1) sq += __shfl_xor_sync(0xffffffffu, sq, o);
    __shared__ float ws[4];
    __shared__ float rinv;
    if ((d & 31) == 0) ws[d >> 5] = sq;
    __syncthreads();
    if (d == 0)
        rinv = rsqrtf((ws[0] + ws[1] + ws[2] + ws[3]) * (1.0f / 128.0f) + RMSEPS);
    __syncthreads();

    const float w = isq ? qw[d] : kw[d];
    float xn = x * rinv * w;

    __shared__ float xs[128];
    xs[d] = xn;
    __syncthreads();

    const int j = d & 63;
    const float c  = cosb[(size_t)s * 64 + j];
    const float sn = sinb[(size_t)s * 64 + j];
    float o;
    if (d < 64) o = xs[d] * c - xs[d + 64] * sn;
    else        o = xs[j] * sn + xs[j + 64] * c;

    if (isq)
        g_q[(size_t)s * (NHQ * HDIM) + hh * HDIM + d] = tf32r(o * QSCALE);
    else
        g_k[(size_t)s * (NKVH * HDIM) + (hh - 16) * HDIM + d] = tf32r(o);
}

// ---------------------------------------------------------------------------
// Causal softmax in place; writes tf32-rounded probs, zeros for t>s.
// ---------------------------------------------------------------------------
__global__ void __launch_bounds__(256) k_softmax()
{
    const int s = blockIdx.x, h = blockIdx.y;
    float* row = g_scores + ((size_t)h * SQ + s) * SQ;
    const int n = s + 1;
    const int tid = threadIdx.x;

    __shared__ float r1[8], r2[8];

    float m = -3.4e38f;
    for (int t = tid; t < n; t += 256) m = fmaxf(m, row[t]);
#pragma unroll
    for (int o = 16; o; o >>= 1) m = fmaxf(m, __shfl_xor_sync(0xffffffffu, m, o));
    if ((tid & 31) == 0) r1[tid >> 5] = m;
    __syncthreads();
    m = r1[0];
#pragma unroll
    for (int i = 1; i < 8; i++) m = fmaxf(m, r1[i]);

    float sum = 0.f;
    for (int t = tid; t < n; t += 256) {
        float e = expf(row[t] - m);
        row[t] = e;
        sum += e;
    }
#pragma unroll
    for (int o = 16; o; o >>= 1) sum += __shfl_xor_sync(0xffffffffu, sum, o);
    if ((tid & 31) == 0) r2[tid >> 5] = sum;
    __syncthreads();
    sum = 0.f;
#pragma unroll
    for (int i = 0; i < 8; i++) sum += r2[i];
    const float inv = 1.0f / sum;

    for (int t = tid; t < SQ; t += 256)
        row[t] = (t < n) ? tf32r(row[t] * inv) : 0.f;
}

// ---------------------------------------------------------------------------
// Launch
// ---------------------------------------------------------------------------
extern "C" void kernel_launch(void* const* d_in, const int* in_sizes, int n_in,
                              void* d_out, int out_size)
{
    const float* hidden = (const float*)d_in[0];
    const float* cosb   = (const float*)d_in[1];
    const float* sinb   = (const float*)d_in[2];
    const float* wqkv   = (const float*)d_in[6];
    const float* bqkv   = (const float*)d_in[7];
    const float* wo     = (const float*)d_in[8];
    const float* bo     = (const float*)d_in[9];
    const float* qw     = (const float*)d_in[10];
    const float* kw     = (const float*)d_in[11];
    float* out = (float*)d_out;

    cudaFuncSetAttribute(k_qkv1,   cudaFuncAttributeMaxDynamicSharedMemorySize, GSMEM);
    cudaFuncSetAttribute(k_qkv2,   cudaFuncAttributeMaxDynamicSharedMemorySize, GSMEM);
    cudaFuncSetAttribute(k_qkv3,   cudaFuncAttributeMaxDynamicSharedMemorySize, GSMEM);
    cudaFuncSetAttribute(k_scores, cudaFuncAttributeMaxDynamicSharedMemorySize, GSMEM);
    cudaFuncSetAttribute(k_pv,     cudaFuncAttributeMaxDynamicSharedMemorySize, GSMEM);
    cudaFuncSetAttribute(k_out,    cudaFuncAttributeMaxDynamicSharedMemorySize, GSMEM);

    // tf32 prep: hi/lo splits (3xTF32 QKV) + wo rounding
    k_split_h<<<(SQ * HIDD + 255) / 256, 256>>>(hidden);
    k_split_w<<<(QKVN * HIDD + 255) / 256, 256>>>(wqkv);
    k_cvt_wo<<<(HIDD * HIDD + 255) / 256, 256>>>(wo);

    // QKV = hid*wqkv^T + b via 3xTF32 (hi*hi + hi*lo + lo*hi)
    dim3 gq(QKVN / 128, SQ / 128);
    k_qkv1<<<gq, 256, GSMEM>>>(bqkv);
    k_qkv2<<<gq, 256, GSMEM>>>();
    k_qkv3<<<gq, 256, GSMEM>>>();

    // RMSNorm + RoPE (+scale) -> tf32 q/k; V transposed -> tf32 vT
    k_norm_rope<<<dim3(SQ, NHQ + NKVH), 128>>>(cosb, sinb, qw, kw);
    k_vT<<<dim3(NKVH * HDIM / 32, SQ / 32), dim3(32, 8)>>>();

    // Scores (causal tile skip), softmax, PV
    k_scores<<<dim3(SQ / 128, SQ / 128, NHQ), 256, GSMEM>>>();
    k_softmax<<<dim3(SQ, NHQ), 256>>>();
    k_pv<<<dim3(1, SQ / 128, NHQ), 256, GSMEM>>>();

    // Output projection
    k_out<<<dim3(HIDD / 128, SQ / 128), 256, GSMEM>>>(bo, out);

    (void)in_sizes; (void)n_in; (void)out_size;
}

// round 9
// speedup vs baseline: 2.6019x; 1.2254x over previous
#include <cuda_runtime.h>
#include <cstddef>
#include <cstdint>

#define SQ    2048
#define HIDD  2048
#define NHQ   16
#define NKVH  4
#define HDIM  128
#define QKVN  3072
#define QSCALE 0.08838834764831845f
#define RMSEPS 1e-6f

// ---------------------------------------------------------------------------
// Scratch (static device globals; allocation is forbidden)
// ---------------------------------------------------------------------------
__device__ float g_qkv   [(size_t)SQ * QKVN];
__device__ float g_q     [(size_t)SQ * NHQ * HDIM];     // tf32-rounded
__device__ float g_k     [(size_t)SQ * NKVH * HDIM];    // tf32-rounded
__device__ float g_vT    [(size_t)NKVH * HDIM * SQ];    // V^T, tf32-rounded
__device__ float g_scores[(size_t)NHQ * SQ * SQ];       // scores -> probs (tf32)
__device__ float g_attn  [(size_t)SQ * NHQ * HDIM];     // tf32-rounded
__device__ float g_hhi   [(size_t)SQ * HIDD];           // hidden, tf32-rounded
__device__ float g_whi   [(size_t)QKVN * HIDD];         // wqkv hi/lo split
__device__ float g_wlo   [(size_t)QKVN * HIDD];
__device__ float g_wot   [(size_t)HIDD * HIDD];         // wo tf32-rounded

// ---------------------------------------------------------------------------
// Helpers
// ---------------------------------------------------------------------------
__device__ __forceinline__ float tf32r(float x) {
    unsigned u;
    asm("cvt.rna.tf32.f32 %0, %1;" : "=r"(u) : "f"(x));
    return __uint_as_float(u);
}

__device__ __forceinline__ void cp16(uint32_t dst, const float* src) {
    asm volatile("cp.async.cg.shared.global [%0], [%1], 16;\n" :: "r"(dst), "l"(src));
}

__device__ __forceinline__ void ldm4(uint32_t* r, uint32_t addr) {
    asm volatile("ldmatrix.sync.aligned.m8n8.x4.shared.b16 {%0,%1,%2,%3}, [%4];\n"
                 : "=r"(r[0]), "=r"(r[1]), "=r"(r[2]), "=r"(r[3]) : "r"(addr));
}

__device__ __forceinline__ void mma8(float* c, const uint32_t* a,
                                     uint32_t b0, uint32_t b1) {
    asm volatile(
        "mma.sync.aligned.m16n8k8.row.col.f32.tf32.tf32.f32 "
        "{%0,%1,%2,%3}, {%4,%5,%6,%7}, {%8,%9}, {%0,%1,%2,%3};\n"
        : "+f"(c[0]), "+f"(c[1]), "+f"(c[2]), "+f"(c[3])
        : "r"(a[0]), "r"(a[1]), "r"(a[2]), "r"(a[3]), "r"(b0), "r"(b1));
}

// ---------------------------------------------------------------------------
// tf32 GEMM core: C = A * B^T (+bias)(+=C)(tf32-round out), tiles 128x128x32.
// 256 threads, 8 warps, warp tile 64x32. 3-stage cp.async pipeline with a
// single __syncthreads per k-tile; ldmatrix fragments; stride-36 padded smem.
// ---------------------------------------------------------------------------
#define SST    36                       // smem row stride (floats)
#define STAGEF (128 * SST)              // floats per matrix per stage
#define SSTB   (2 * STAGEF * 4)         // bytes per stage (A+B)
#define GSMEM  (3 * SSTB)               // 110592 bytes

__device__ __forceinline__ void cp_stage(const float* Ag, const float* Bg,
                                         int lda, int ldb,
                                         uint32_t dA, uint32_t dB) {
#pragma unroll
    for (int i = 0; i < 4; i++) {
        cp16(dA + i * 32 * SST * 4, Ag + (size_t)(i * 32) * lda);
        cp16(dB + i * 32 * SST * 4, Bg + (size_t)(i * 32) * ldb);
    }
}

__device__ __forceinline__ void gemm_core(
    const float* __restrict__ A, int lda,
    const float* __restrict__ B, int ldb,
    float* __restrict__ C, int ldc,
    int K, const float* __restrict__ bias,
    int accum, int cvt, int bx, int by)
{
    extern __shared__ float dsm[];
    const int tid  = threadIdx.x;
    const int wid  = tid >> 5, lane = tid & 31;
    const int wm   = (wid & 1) * 64, wn = (wid >> 1) * 32;
    const int ldrw = tid >> 3, ldcl = (tid & 7) * 4;

    const uint32_t sb = (uint32_t)__cvta_generic_to_shared(dsm);
    const float* Ag = A + (size_t)(by * 128 + ldrw) * lda + ldcl;
    const float* Bg = B + (size_t)(bx * 128 + ldrw) * ldb + ldcl;
    const uint32_t dA0 = sb + (ldrw * SST + ldcl) * 4;

    const int nK = K >> 5;

    float acc[4][4][4];
#pragma unroll
    for (int a = 0; a < 4; a++)
#pragma unroll
        for (int b = 0; b < 4; b++)
#pragma unroll
            for (int c = 0; c < 4; c++) acc[a][b][c] = 0.f;

    const int mi  = lane >> 3, l7 = lane & 7;
    const int aro = (mi & 1) * 8 + l7, aco = (mi >> 1) * 4;
    const int bro = (mi >> 1) * 8 + l7, bco = (mi & 1) * 4;

    // Prologue: stages 0, 1
    cp_stage(Ag, Bg, lda, ldb, dA0, dA0 + STAGEF * 4);
    asm volatile("cp.async.commit_group;\n");
    if (nK > 1)
        cp_stage(Ag + 32, Bg + 32, lda, ldb, dA0 + SSTB, dA0 + SSTB + STAGEF * 4);
    asm volatile("cp.async.commit_group;\n");

    for (int kt = 0; kt < nK; kt++) {
        asm volatile("cp.async.wait_group 1;\n");
        __syncthreads();

        // Prefetch stage kt+2 (its buffer was consumed in iteration kt-1,
        // which is ordered before this point by the barrier above).
        if (kt + 2 < nK) {
            const int sti = (kt + 2) % 3;
            cp_stage(Ag + (kt + 2) * 32, Bg + (kt + 2) * 32, lda, ldb,
                     dA0 + sti * SSTB, dA0 + sti * SSTB + STAGEF * 4);
        }
        asm volatile("cp.async.commit_group;\n");

        const uint32_t sA = sb + (kt % 3) * SSTB;
        const uint32_t sB = sA + STAGEF * 4;
#pragma unroll
        for (int k = 0; k < 32; k += 8) {
            uint32_t bq[8];
            ldm4(bq,     sB + ((wn +      bro) * SST + k + bco) * 4);
            ldm4(bq + 4, sB + ((wn + 16 + bro) * SST + k + bco) * 4);
#pragma unroll
            for (int mt = 0; mt < 4; mt++) {
                uint32_t aq[4];
                ldm4(aq, sA + ((wm + 16 * mt + aro) * SST + k + aco) * 4);
                mma8(acc[mt][0], aq, bq[0], bq[1]);
                mma8(acc[mt][1], aq, bq[2], bq[3]);
                mma8(acc[mt][2], aq, bq[4], bq[5]);
                mma8(acc[mt][3], aq, bq[6], bq[7]);
            }
        }
    }

    // Epilogue
    const int g = lane >> 2, tg = lane & 3;
#pragma unroll
    for (int mt = 0; mt < 4; mt++) {
#pragma unroll
        for (int nt = 0; nt < 4; nt++) {
            const int r0 = by * 128 + wm + 16 * mt + g;
            const int c0 = bx * 128 + wn + 8 * nt + tg * 2;
            float x0 = acc[mt][nt][0], x1 = acc[mt][nt][1];
            float x2 = acc[mt][nt][2], x3 = acc[mt][nt][3];
            if (bias) {
                float b0 = bias[c0], b1 = bias[c0 + 1];
                x0 += b0; x1 += b1; x2 += b0; x3 += b1;
            }
            float2* p0 = reinterpret_cast<float2*>(C + (size_t)r0 * ldc + c0);
            float2* p1 = reinterpret_cast<float2*>(C + (size_t)(r0 + 8) * ldc + c0);
            if (accum) {
                float2 o0 = *p0, o1 = *p1;
                x0 += o0.x; x1 += o0.y; x2 += o1.x; x3 += o1.y;
            }
            if (cvt) { x0 = tf32r(x0); x1 = tf32r(x1); x2 = tf32r(x2); x3 = tf32r(x3); }
            *p0 = make_float2(x0, x1);
            *p1 = make_float2(x2, x3);
        }
    }
}

// ---------------------------------------------------------------------------
// GEMM kernels
// ---------------------------------------------------------------------------
__global__ void __launch_bounds__(256, 2) k_qkv1(const float* __restrict__ bias) {
    gemm_core(g_hhi, HIDD, g_whi, HIDD, g_qkv, QKVN, HIDD, bias, 0, 0,
              blockIdx.x, blockIdx.y);
}
__global__ void __launch_bounds__(256, 2) k_qkv2() {
    gemm_core(g_hhi, HIDD, g_wlo, HIDD, g_qkv, QKVN, HIDD, nullptr, 1, 0,
              blockIdx.x, blockIdx.y);
}
__global__ void __launch_bounds__(256, 2) k_scores() {
    const int bx = blockIdx.x, by = blockIdx.y, h = blockIdx.z;
    if (bx > by) return;  // entirely above causal diagonal
    gemm_core(g_q + h * HDIM, NHQ * HDIM,
              g_k + (h >> 2) * HDIM, NKVH * HDIM,
              g_scores + (size_t)h * SQ * SQ, SQ, HDIM, nullptr, 0, 0, bx, by);
}
__global__ void __launch_bounds__(256, 2) k_pv() {
    const int by = blockIdx.y, h = blockIdx.z;
    const int kmax = (by + 1) * 128;  // p[s,t]=0 for t>s
    gemm_core(g_scores + (size_t)h * SQ * SQ, SQ,
              g_vT + (size_t)(h >> 2) * HDIM * SQ, SQ,
              g_attn + h * HDIM, NHQ * HDIM, kmax, nullptr, 0, 1, 0, by);
}
__global__ void __launch_bounds__(256, 2) k_out(const float* __restrict__ bo,
                                                float* __restrict__ out) {
    gemm_core(g_attn, NHQ * HDIM, g_wot, HIDD, out, HIDD, HIDD, bo, 0, 0,
              blockIdx.x, blockIdx.y);
}

// ---------------------------------------------------------------------------
// tf32 prep kernels
// ---------------------------------------------------------------------------
__global__ void __launch_bounds__(256) k_round_h(const float* __restrict__ x) {
    int i = blockIdx.x * 256 + threadIdx.x;
    if (i < SQ * HIDD) g_hhi[i] = tf32r(x[i]);
}
__global__ void __launch_bounds__(256) k_split_w(const float* __restrict__ x) {
    int i = blockIdx.x * 256 + threadIdx.x;
    if (i < QKVN * HIDD) {
        float v = x[i], h = tf32r(v);
        g_whi[i] = h; g_wlo[i] = tf32r(v - h);
    }
}
__global__ void __launch_bounds__(256) k_cvt_wo(const float* __restrict__ x) {
    int i = blockIdx.x * 256 + threadIdx.x;
    if (i < HIDD * HIDD) g_wot[i] = tf32r(x[i]);
}

// V transpose: g_vT[c][s] = tf32(g_qkv[s][2560 + c]),  c in [0, 512)
__global__ void __launch_bounds__(256) k_vT() {
    __shared__ float t[32][33];
    const int c0 = blockIdx.x * 32, s0 = blockIdx.y * 32;
    const int tx = threadIdx.x, ty = threadIdx.y;  // 32 x 8
#pragma unroll
    for (int j = 0; j < 32; j += 8)
        t[ty + j][tx] = g_qkv[(size_t)(s0 + ty + j) * QKVN
                              + (NHQ + NKVH) * HDIM + c0 + tx];
    __syncthreads();
#pragma unroll
    for (int j = 0; j < 32; j += 8)
        g_vT[(size_t)(c0 + ty + j) * SQ + s0 + tx] = tf32r(t[tx][ty + j]);
}

// ---------------------------------------------------------------------------
// RMSNorm + RoPE (+q scaling), outputs tf32-rounded. grid (S, 20), 128 thr.
// ---------------------------------------------------------------------------
__global__ void __launch_bounds__(128) k_norm_rope(
    const float* __restrict__ cosb, const float* __restrict__ sinb,
    const float* __restrict__ qw,   const float* __restrict__ kw)
{
    const int s  = blockIdx.x;
    const int hh = blockIdx.y;       // [0,16): q head; [16,20): k head
    const int d  = threadIdx.x;
    const float* row = g_qkv + (size_t)s * QKVN;

    const bool isq = (hh < 16);
    const int off = isq ? hh * HDIM : NHQ * HDIM + (hh - 16) * HDIM;
    float x = row[off + d];

    float sq = x * x;
#pragma unroll
    for (int o = 16; o; o >>= 1) sq += __shfl_xor_sync(0xffffffffu, sq, o);
    __shared__ float ws[4];
    __shared__ float rinv;
    if ((d & 31) == 0) ws[d >> 5] = sq;
    __syncthreads();
    if (d == 0)
        rinv = rsqrtf((ws[0] + ws[1] + ws[2] + ws[3]) * (1.0f / 128.0f) + RMSEPS);
    __syncthreads();

    const float w = isq ? qw[d] : kw[d];
    float xn = x * rinv * w;

    __shared__ float xs[128];
    xs[d] = xn;
    __syncthreads();

    const int j = d & 63;
    const float c  = cosb[(size_t)s * 64 + j];
    const float sn = sinb[(size_t)s * 64 + j];
    float o;
    if (d < 64) o = xs[d] * c - xs[d + 64] * sn;
    else        o = xs[j] * sn + xs[j + 64] * c;

    if (isq)
        g_q[(size_t)s * (NHQ * HDIM) + hh * HDIM + d] = tf32r(o * QSCALE);
    else
        g_k[(size_t)s * (NKVH * HDIM) + (hh - 16) * HDIM + d] = tf32r(o);
}

// ---------------------------------------------------------------------------
// Causal softmax in place; tf32-rounded probs; zeros only up to the 128-tile
// edge (PV never reads past kmax for this row block).
// ---------------------------------------------------------------------------
__global__ void __launch_bounds__(256) k_softmax()
{
    const int s = blockIdx.x, h = blockIdx.y;
    float* row = g_scores + ((size_t)h * SQ + s) * SQ;
    const int n = s + 1;
    const int kmax = ((s >> 7) + 1) << 7;   // 128-aligned upper bound PV reads
    const int tid = threadIdx.x;

    __shared__ float r1[8], r2[8];

    float m = -3.4e38f;
    for (int t = tid; t < n; t += 256) m = fmaxf(m, row[t]);
#pragma unroll
    for (int o = 16; o; o >>= 1) m = fmaxf(m, __shfl_xor_sync(0xffffffffu, m, o));
    if ((tid & 31) == 0) r1[tid >> 5] = m;
    __syncthreads();
    m = r1[0];
#pragma unroll
    for (int i = 1; i < 8; i++) m = fmaxf(m, r1[i]);

    float sum = 0.f;
    for (int t = tid; t < n; t += 256) {
        float e = expf(row[t] - m);
        row[t] = e;
        sum += e;
    }
#pragma unroll
    for (int o = 16; o; o >>= 1) sum += __shfl_xor_sync(0xffffffffu, sum, o);
    if ((tid & 31) == 0) r2[tid >> 5] = sum;
    __syncthreads();
    sum = 0.f;
#pragma unroll
    for (int i = 0; i < 8; i++) sum += r2[i];
    const float inv = 1.0f / sum;

    for (int t = tid; t < kmax; t += 256)
        row[t] = (t < n) ? tf32r(row[t] * inv) : 0.f;
}

// ---------------------------------------------------------------------------
// Launch
// ---------------------------------------------------------------------------
extern "C" void kernel_launch(void* const* d_in, const int* in_sizes, int n_in,
                              void* d_out, int out_size)
{
    const float* hidden = (const float*)d_in[0];
    const float* cosb   = (const float*)d_in[1];
    const float* sinb   = (const float*)d_in[2];
    const float* wqkv   = (const float*)d_in[6];
    const float* bqkv   = (const float*)d_in[7];
    const float* wo     = (const float*)d_in[8];
    const float* bo     = (const float*)d_in[9];
    const float* qw     = (const float*)d_in[10];
    const float* kw     = (const float*)d_in[11];
    float* out = (float*)d_out;

    cudaFuncSetAttribute(k_qkv1,   cudaFuncAttributeMaxDynamicSharedMemorySize, GSMEM);
    cudaFuncSetAttribute(k_qkv2,   cudaFuncAttributeMaxDynamicSharedMemorySize, GSMEM);
    cudaFuncSetAttribute(k_scores, cudaFuncAttributeMaxDynamicSharedMemorySize, GSMEM);
    cudaFuncSetAttribute(k_pv,     cudaFuncAttributeMaxDynamicSharedMemorySize, GSMEM);
    cudaFuncSetAttribute(k_out,    cudaFuncAttributeMaxDynamicSharedMemorySize, GSMEM);

    // tf32 prep
    k_round_h<<<(SQ * HIDD + 255) / 256, 256>>>(hidden);
    k_split_w<<<(QKVN * HIDD + 255) / 256, 256>>>(wqkv);
    k_cvt_wo<<<(HIDD * HIDD + 255) / 256, 256>>>(wo);

    // QKV = h_hi*(w_hi + w_lo)^T + b  (2-pass tf32; dropped h_lo term ~1.4e-4)
    dim3 gq(QKVN / 128, SQ / 128);
    k_qkv1<<<gq, 256, GSMEM>>>(bqkv);
    k_qkv2<<<gq, 256, GSMEM>>>();

    // RMSNorm + RoPE (+scale) -> tf32 q/k; V transposed -> tf32 vT
    k_norm_rope<<<dim3(SQ, NHQ + NKVH), 128>>>(cosb, sinb, qw, kw);
    k_vT<<<dim3(NKVH * HDIM / 32, SQ / 32), dim3(32, 8)>>>();

    // Scores (causal tile skip), softmax, PV
    k_scores<<<dim3(SQ / 128, SQ / 128, NHQ), 256, GSMEM>>>();
    k_softmax<<<dim3(SQ, NHQ), 256>>>();
    k_pv<<<dim3(1, SQ / 128, NHQ), 256, GSMEM>>>();

    // Output projection
    k_out<<<dim3(HIDD / 128, SQ / 128), 256, GSMEM>>>(bo, out);

    (void)in_sizes; (void)n_in; (void)out_size;
}

// round 10
// speedup vs baseline: 2.6611x; 1.0228x over previous
#include <cuda_runtime.h>
#include <cstddef>
#include <cstdint>

#define SQ    2048
#define HIDD  2048
#define NHQ   16
#define NKVH  4
#define HDIM  128
#define QKVN  3072
#define QSCALE 0.08838834764831845f
#define RMSEPS 1e-6f

// ---------------------------------------------------------------------------
// Scratch (static device globals; allocation is forbidden)
// ---------------------------------------------------------------------------
__device__ float g_qkv   [(size_t)SQ * QKVN];
__device__ float g_q     [(size_t)SQ * NHQ * HDIM];     // tf32-rounded
__device__ float g_k     [(size_t)SQ * NKVH * HDIM];    // tf32-rounded
__device__ float g_vT    [(size_t)NKVH * HDIM * SQ];    // V^T, tf32-rounded
__device__ float g_scores[(size_t)NHQ * SQ * SQ];       // scores -> probs (tf32)
__device__ float g_attn  [(size_t)SQ * NHQ * HDIM];     // tf32-rounded
__device__ float g_hhi   [(size_t)SQ * HIDD];           // hidden, tf32-rounded
__device__ float g_whi   [(size_t)QKVN * HIDD];         // wqkv hi/lo split
__device__ float g_wlo   [(size_t)QKVN * HIDD];
__device__ float g_wot   [(size_t)HIDD * HIDD];         // wo tf32-rounded

// ---------------------------------------------------------------------------
// Helpers
// ---------------------------------------------------------------------------
__device__ __forceinline__ float tf32r(float x) {
    unsigned u;
    asm("cvt.rna.tf32.f32 %0, %1;" : "=r"(u) : "f"(x));
    return __uint_as_float(u);
}

__device__ __forceinline__ void cp16(uint32_t dst, const float* src) {
    asm volatile("cp.async.cg.shared.global [%0], [%1], 16;\n" :: "r"(dst), "l"(src));
}

__device__ __forceinline__ void ldm4(uint32_t* r, uint32_t addr) {
    asm volatile("ldmatrix.sync.aligned.m8n8.x4.shared.b16 {%0,%1,%2,%3}, [%4];\n"
                 : "=r"(r[0]), "=r"(r[1]), "=r"(r[2]), "=r"(r[3]) : "r"(addr));
}

__device__ __forceinline__ void mma8(float* c, const uint32_t* a,
                                     uint32_t b0, uint32_t b1) {
    asm volatile(
        "mma.sync.aligned.m16n8k8.row.col.f32.tf32.tf32.f32 "
        "{%0,%1,%2,%3}, {%4,%5,%6,%7}, {%8,%9}, {%0,%1,%2,%3};\n"
        : "+f"(c[0]), "+f"(c[1]), "+f"(c[2]), "+f"(c[3])
        : "r"(a[0]), "r"(a[1]), "r"(a[2]), "r"(a[3]), "r"(b0), "r"(b1));
}

#define SST    36                       // smem row stride (floats)
#define STAGEF (128 * SST)              // floats per matrix per stage
#define SSTB   (2 * STAGEF * 4)         // bytes per stage (A+B)
#define GSMEM  (3 * SSTB)               // generic core: 3 stages = 110592 B
#define FSTGB  (3 * STAGEF * 4)         // fused stage bytes (A+Bhi+Blo)
#define FSMEM  (2 * FSTGB)              // fused: 2 stages = 110592 B

// ---------------------------------------------------------------------------
// Generic tf32 GEMM core: C = A * B^T (+bias)(+=C)(tf32 out), 128x128x32,
// 3-stage cp.async, single barrier per k-tile.
// ---------------------------------------------------------------------------
__device__ __forceinline__ void cp_stage(const float* Ag, const float* Bg,
                                         int lda, int ldb,
                                         uint32_t dA, uint32_t dB) {
#pragma unroll
    for (int i = 0; i < 4; i++) {
        cp16(dA + i * 32 * SST * 4, Ag + (size_t)(i * 32) * lda);
        cp16(dB + i * 32 * SST * 4, Bg + (size_t)(i * 32) * ldb);
    }
}

__device__ __forceinline__ void gemm_core(
    const float* __restrict__ A, int lda,
    const float* __restrict__ B, int ldb,
    float* __restrict__ C, int ldc,
    int K, const float* __restrict__ bias,
    int accum, int cvt, int bx, int by)
{
    extern __shared__ float dsm[];
    const int tid  = threadIdx.x;
    const int wid  = tid >> 5, lane = tid & 31;
    const int wm   = (wid & 1) * 64, wn = (wid >> 1) * 32;
    const int ldrw = tid >> 3, ldcl = (tid & 7) * 4;

    const uint32_t sb = (uint32_t)__cvta_generic_to_shared(dsm);
    const float* Ag = A + (size_t)(by * 128 + ldrw) * lda + ldcl;
    const float* Bg = B + (size_t)(bx * 128 + ldrw) * ldb + ldcl;
    const uint32_t dA0 = sb + (ldrw * SST + ldcl) * 4;

    const int nK = K >> 5;

    float acc[4][4][4];
#pragma unroll
    for (int a = 0; a < 4; a++)
#pragma unroll
        for (int b = 0; b < 4; b++)
#pragma unroll
            for (int c = 0; c < 4; c++) acc[a][b][c] = 0.f;

    const int mi  = lane >> 3, l7 = lane & 7;
    const int aro = (mi & 1) * 8 + l7, aco = (mi >> 1) * 4;
    const int bro = (mi >> 1) * 8 + l7, bco = (mi & 1) * 4;

    cp_stage(Ag, Bg, lda, ldb, dA0, dA0 + STAGEF * 4);
    asm volatile("cp.async.commit_group;\n");
    if (nK > 1)
        cp_stage(Ag + 32, Bg + 32, lda, ldb, dA0 + SSTB, dA0 + SSTB + STAGEF * 4);
    asm volatile("cp.async.commit_group;\n");

    for (int kt = 0; kt < nK; kt++) {
        asm volatile("cp.async.wait_group 1;\n");
        __syncthreads();

        if (kt + 2 < nK) {
            const int sti = (kt + 2) % 3;
            cp_stage(Ag + (kt + 2) * 32, Bg + (kt + 2) * 32, lda, ldb,
                     dA0 + sti * SSTB, dA0 + sti * SSTB + STAGEF * 4);
        }
        asm volatile("cp.async.commit_group;\n");

        const uint32_t sA = sb + (kt % 3) * SSTB;
        const uint32_t sB = sA + STAGEF * 4;
#pragma unroll
        for (int k = 0; k < 32; k += 8) {
            uint32_t bq[8];
            ldm4(bq,     sB + ((wn +      bro) * SST + k + bco) * 4);
            ldm4(bq + 4, sB + ((wn + 16 + bro) * SST + k + bco) * 4);
#pragma unroll
            for (int mt = 0; mt < 4; mt++) {
                uint32_t aq[4];
                ldm4(aq, sA + ((wm + 16 * mt + aro) * SST + k + aco) * 4);
                mma8(acc[mt][0], aq, bq[0], bq[1]);
                mma8(acc[mt][1], aq, bq[2], bq[3]);
                mma8(acc[mt][2], aq, bq[4], bq[5]);
                mma8(acc[mt][3], aq, bq[6], bq[7]);
            }
        }
    }

    const int g = lane >> 2, tg = lane & 3;
#pragma unroll
    for (int mt = 0; mt < 4; mt++) {
#pragma unroll
        for (int nt = 0; nt < 4; nt++) {
            const int r0 = by * 128 + wm + 16 * mt + g;
            const int c0 = bx * 128 + wn + 8 * nt + tg * 2;
            float x0 = acc[mt][nt][0], x1 = acc[mt][nt][1];
            float x2 = acc[mt][nt][2], x3 = acc[mt][nt][3];
            if (bias) {
                float b0 = bias[c0], b1 = bias[c0 + 1];
                x0 += b0; x1 += b1; x2 += b0; x3 += b1;
            }
            float2* p0 = reinterpret_cast<float2*>(C + (size_t)r0 * ldc + c0);
            float2* p1 = reinterpret_cast<float2*>(C + (size_t)(r0 + 8) * ldc + c0);
            if (accum) {
                float2 o0 = *p0, o1 = *p1;
                x0 += o0.x; x1 += o0.y; x2 += o1.x; x3 += o1.y;
            }
            if (cvt) { x0 = tf32r(x0); x1 = tf32r(x1); x2 = tf32r(x2); x3 = tf32r(x3); }
            *p0 = make_float2(x0, x1);
            *p1 = make_float2(x2, x3);
        }
    }
}

// ---------------------------------------------------------------------------
// Fused QKV: C = A*(Bhi)^T + A*(Blo)^T + bias in ONE pass.
// Same accumulators for both B matrices; A fragments loaded once.
// 2-stage pipeline, stage = [A | Bhi | Blo].
// ---------------------------------------------------------------------------
__global__ void __launch_bounds__(256, 2) k_qkv_fused(const float* __restrict__ bias)
{
    extern __shared__ float dsm[];
    const int bx = blockIdx.x, by = blockIdx.y;
    const int tid  = threadIdx.x;
    const int wid  = tid >> 5, lane = tid & 31;
    const int wm   = (wid & 1) * 64, wn = (wid >> 1) * 32;
    const int ldrw = tid >> 3, ldcl = (tid & 7) * 4;

    const uint32_t sb = (uint32_t)__cvta_generic_to_shared(dsm);
    const float* Ag = g_hhi + (size_t)(by * 128 + ldrw) * HIDD + ldcl;
    const float* Bh = g_whi + (size_t)(bx * 128 + ldrw) * HIDD + ldcl;
    const float* Bl = g_wlo + (size_t)(bx * 128 + ldrw) * HIDD + ldcl;
    const uint32_t dA0 = sb + (ldrw * SST + ldcl) * 4;

    const int nK = HIDD >> 5;   // 64

    float acc[4][4][4];
#pragma unroll
    for (int a = 0; a < 4; a++)
#pragma unroll
        for (int b = 0; b < 4; b++)
#pragma unroll
            for (int c = 0; c < 4; c++) acc[a][b][c] = 0.f;

    const int mi  = lane >> 3, l7 = lane & 7;
    const int aro = (mi & 1) * 8 + l7, aco = (mi >> 1) * 4;
    const int bro = (mi >> 1) * 8 + l7, bco = (mi & 1) * 4;

    // prologue: stage 0
#pragma unroll
    for (int i = 0; i < 4; i++) {
        cp16(dA0 + (0 * STAGEF + i * 32 * SST) * 4, Ag + (size_t)(i * 32) * HIDD);
        cp16(dA0 + (1 * STAGEF + i * 32 * SST) * 4, Bh + (size_t)(i * 32) * HIDD);
        cp16(dA0 + (2 * STAGEF + i * 32 * SST) * 4, Bl + (size_t)(i * 32) * HIDD);
    }
    asm volatile("cp.async.commit_group;\n");

    for (int kt = 0; kt < nK; kt++) {
        if (kt + 1 < nK) {
            const uint32_t d = dA0 + ((kt + 1) & 1) * FSTGB;
            const int ko = (kt + 1) * 32;
#pragma unroll
            for (int i = 0; i < 4; i++) {
                cp16(d + (0 * STAGEF + i * 32 * SST) * 4, Ag + (size_t)(i * 32) * HIDD + ko);
                cp16(d + (1 * STAGEF + i * 32 * SST) * 4, Bh + (size_t)(i * 32) * HIDD + ko);
                cp16(d + (2 * STAGEF + i * 32 * SST) * 4, Bl + (size_t)(i * 32) * HIDD + ko);
            }
            asm volatile("cp.async.commit_group;\n");
            asm volatile("cp.async.wait_group 1;\n");
        } else {
            asm volatile("cp.async.wait_group 0;\n");
        }
        __syncthreads();

        const uint32_t sA  = sb + (kt & 1) * FSTGB;
        const uint32_t sBh = sA + STAGEF * 4;
        const uint32_t sBl = sBh + STAGEF * 4;
#pragma unroll
        for (int k = 0; k < 32; k += 8) {
            uint32_t bh[8], bl[8];
            ldm4(bh,     sBh + ((wn +      bro) * SST + k + bco) * 4);
            ldm4(bh + 4, sBh + ((wn + 16 + bro) * SST + k + bco) * 4);
            ldm4(bl,     sBl + ((wn +      bro) * SST + k + bco) * 4);
            ldm4(bl + 4, sBl + ((wn + 16 + bro) * SST + k + bco) * 4);
#pragma unroll
            for (int mt = 0; mt < 4; mt++) {
                uint32_t aq[4];
                ldm4(aq, sA + ((wm + 16 * mt + aro) * SST + k + aco) * 4);
                mma8(acc[mt][0], aq, bh[0], bh[1]);
                mma8(acc[mt][1], aq, bh[2], bh[3]);
                mma8(acc[mt][2], aq, bh[4], bh[5]);
                mma8(acc[mt][3], aq, bh[6], bh[7]);
                mma8(acc[mt][0], aq, bl[0], bl[1]);
                mma8(acc[mt][1], aq, bl[2], bl[3]);
                mma8(acc[mt][2], aq, bl[4], bl[5]);
                mma8(acc[mt][3], aq, bl[6], bl[7]);
            }
        }
        __syncthreads();
    }

    const int g = lane >> 2, tg = lane & 3;
#pragma unroll
    for (int mt = 0; mt < 4; mt++) {
#pragma unroll
        for (int nt = 0; nt < 4; nt++) {
            const int r0 = by * 128 + wm + 16 * mt + g;
            const int c0 = bx * 128 + wn + 8 * nt + tg * 2;
            float b0 = bias[c0], b1 = bias[c0 + 1];
            *reinterpret_cast<float2*>(g_qkv + (size_t)r0 * QKVN + c0) =
                make_float2(acc[mt][nt][0] + b0, acc[mt][nt][1] + b1);
            *reinterpret_cast<float2*>(g_qkv + (size_t)(r0 + 8) * QKVN + c0) =
                make_float2(acc[mt][nt][2] + b0, acc[mt][nt][3] + b1);
        }
    }
}

// ---------------------------------------------------------------------------
// GEMM wrappers (scores / pv / out use the generic core)
// ---------------------------------------------------------------------------
__global__ void __launch_bounds__(256, 2) k_scores() {
    const int bx = blockIdx.x, by = blockIdx.y, h = blockIdx.z;
    if (bx > by) return;
    gemm_core(g_q + h * HDIM, NHQ * HDIM,
              g_k + (h >> 2) * HDIM, NKVH * HDIM,
              g_scores + (size_t)h * SQ * SQ, SQ, HDIM, nullptr, 0, 0, bx, by);
}
__global__ void __launch_bounds__(256, 2) k_pv() {
    const int by = blockIdx.y, h = blockIdx.z;
    const int kmax = (by + 1) * 128;
    gemm_core(g_scores + (size_t)h * SQ * SQ, SQ,
              g_vT + (size_t)(h >> 2) * HDIM * SQ, SQ,
              g_attn + h * HDIM, NHQ * HDIM, kmax, nullptr, 0, 1, 0, by);
}
__global__ void __launch_bounds__(256, 2) k_out(const float* __restrict__ bo,
                                                float* __restrict__ out) {
    gemm_core(g_attn, NHQ * HDIM, g_wot, HIDD, out, HIDD, HIDD, bo, 0, 0,
              blockIdx.x, blockIdx.y);
}

// ---------------------------------------------------------------------------
// tf32 prep kernels
// ---------------------------------------------------------------------------
__global__ void __launch_bounds__(256) k_round_h(const float* __restrict__ x) {
    int i = blockIdx.x * 256 + threadIdx.x;
    if (i < SQ * HIDD) g_hhi[i] = tf32r(x[i]);
}
__global__ void __launch_bounds__(256) k_split_w(const float* __restrict__ x) {
    int i = blockIdx.x * 256 + threadIdx.x;
    if (i < QKVN * HIDD) {
        float v = x[i], h = tf32r(v);
        g_whi[i] = h; g_wlo[i] = tf32r(v - h);
    }
}
__global__ void __launch_bounds__(256) k_cvt_wo(const float* __restrict__ x) {
    int i = blockIdx.x * 256 + threadIdx.x;
    if (i < HIDD * HIDD) g_wot[i] = tf32r(x[i]);
}

// V transpose: g_vT[c][s] = tf32(g_qkv[s][2560 + c]),  c in [0, 512)
__global__ void __launch_bounds__(256) k_vT() {
    __shared__ float t[32][33];
    const int c0 = blockIdx.x * 32, s0 = blockIdx.y * 32;
    const int tx = threadIdx.x, ty = threadIdx.y;  // 32 x 8
#pragma unroll
    for (int j = 0; j < 32; j += 8)
        t[ty + j][tx] = g_qkv[(size_t)(s0 + ty + j) * QKVN
                              + (NHQ + NKVH) * HDIM + c0 + tx];
    __syncthreads();
#pragma unroll
    for (int j = 0; j < 32; j += 8)
        g_vT[(size_t)(c0 + ty + j) * SQ + s0 + tx] = tf32r(t[tx][ty + j]);
}

// ---------------------------------------------------------------------------
// RMSNorm + RoPE (+q scaling), outputs tf32-rounded. grid (S, 20), 128 thr.
// ---------------------------------------------------------------------------
__global__ void __launch_bounds__(128) k_norm_rope(
    const float* __restrict__ cosb, const float* __restrict__ sinb,
    const float* __restrict__ qw,   const float* __restrict__ kw)
{
    const int s  = blockIdx.x;
    const int hh = blockIdx.y;
    const int d  = threadIdx.x;
    const float* row = g_qkv + (size_t)s * QKVN;

    const bool isq = (hh < 16);
    const int off = isq ? hh * HDIM : NHQ * HDIM + (hh - 16) * HDIM;
    float x = row[off + d];

    float sq = x * x;
#pragma unroll
    for (int o = 16; o; o >>= 1) sq += __shfl_xor_sync(0xffffffffu, sq, o);
    __shared__ float ws[4];
    __shared__ float rinv;
    if ((d & 31) == 0) ws[d >> 5] = sq;
    __syncthreads();
    if (d == 0)
        rinv = rsqrtf((ws[0] + ws[1] + ws[2] + ws[3]) * (1.0f / 128.0f) + RMSEPS);
    __syncthreads();

    const float w = isq ? qw[d] : kw[d];
    float xn = x * rinv * w;

    __shared__ float xs[128];
    xs[d] = xn;
    __syncthreads();

    const int j = d & 63;
    const float c  = cosb[(size_t)s * 64 + j];
    const float sn = sinb[(size_t)s * 64 + j];
    float o;
    if (d < 64) o = xs[d] * c - xs[d + 64] * sn;
    else        o = xs[j] * sn + xs[j + 64] * c;

    if (isq)
        g_q[(size_t)s * (NHQ * HDIM) + hh * HDIM + d] = tf32r(o * QSCALE);
    else
        g_k[(size_t)s * (NKVH * HDIM) + (hh - 16) * HDIM + d] = tf32r(o);
}

// ---------------------------------------------------------------------------
// Online causal softmax: pass1 fused max+sum (rescaling), pass2 exp+normalize.
// Writes tf32 probs; zeros only to the 128-aligned tile edge.
// ---------------------------------------------------------------------------
__global__ void __launch_bounds__(256) k_softmax()
{
    const int s = blockIdx.x, h = blockIdx.y;
    float* row = g_scores + ((size_t)h * SQ + s) * SQ;
    const int n = s + 1;
    const int kmax = ((s >> 7) + 1) << 7;
    const int tid = threadIdx.x;
    const int lane = tid & 31, w = tid >> 5;

    float m = -3.4e38f, ssum = 0.f;
    for (int t = tid; t < n; t += 256) {
        float x = row[t];
        float nm = fmaxf(m, x);
        ssum = ssum * expf(m - nm) + expf(x - nm);
        m = nm;
    }
#pragma unroll
    for (int o = 16; o; o >>= 1) {
        float om = __shfl_xor_sync(0xffffffffu, m, o);
        float os = __shfl_xor_sync(0xffffffffu, ssum, o);
        float nm = fmaxf(m, om);
        ssum = ssum * expf(m - nm) + os * expf(om - nm);
        m = nm;
    }
    __shared__ float sm[8], ss[8];
    if (lane == 0) { sm[w] = m; ss[w] = ssum; }
    __syncthreads();
    float M = sm[0], S = ss[0];
#pragma unroll
    for (int i = 1; i < 8; i++) {
        float nm = fmaxf(M, sm[i]);
        S = S * expf(M - nm) + ss[i] * expf(sm[i] - nm);
        M = nm;
    }
    const float inv = 1.0f / S;

    for (int t = tid; t < kmax; t += 256)
        row[t] = (t < n) ? tf32r(expf(row[t] - M) * inv) : 0.f;
}

// ---------------------------------------------------------------------------
// Launch
// ---------------------------------------------------------------------------
extern "C" void kernel_launch(void* const* d_in, const int* in_sizes, int n_in,
                              void* d_out, int out_size)
{
    const float* hidden = (const float*)d_in[0];
    const float* cosb   = (const float*)d_in[1];
    const float* sinb   = (const float*)d_in[2];
    const float* wqkv   = (const float*)d_in[6];
    const float* bqkv   = (const float*)d_in[7];
    const float* wo     = (const float*)d_in[8];
    const float* bo     = (const float*)d_in[9];
    const float* qw     = (const float*)d_in[10];
    const float* kw     = (const float*)d_in[11];
    float* out = (float*)d_out;

    cudaFuncSetAttribute(k_qkv_fused, cudaFuncAttributeMaxDynamicSharedMemorySize, FSMEM);
    cudaFuncSetAttribute(k_scores,    cudaFuncAttributeMaxDynamicSharedMemorySize, GSMEM);
    cudaFuncSetAttribute(k_pv,        cudaFuncAttributeMaxDynamicSharedMemorySize, GSMEM);
    cudaFuncSetAttribute(k_out,       cudaFuncAttributeMaxDynamicSharedMemorySize, GSMEM);

    // tf32 prep
    k_round_h<<<(SQ * HIDD + 255) / 256, 256>>>(hidden);
    k_split_w<<<(QKVN * HIDD + 255) / 256, 256>>>(wqkv);
    k_cvt_wo<<<(HIDD * HIDD + 255) / 256, 256>>>(wo);

    // QKV = h_hi*(w_hi^T + w_lo^T) + b, single fused pass
    k_qkv_fused<<<dim3(QKVN / 128, SQ / 128), 256, FSMEM>>>(bqkv);

    // RMSNorm + RoPE (+scale) -> tf32 q/k; V transposed -> tf32 vT
    k_norm_rope<<<dim3(SQ, NHQ + NKVH), 128>>>(cosb, sinb, qw, kw);
    k_vT<<<dim3(NKVH * HDIM / 32, SQ / 32), dim3(32, 8)>>>();

    // Scores (causal tile skip), online softmax, PV
    k_scores<<<dim3(SQ / 128, SQ / 128, NHQ), 256, GSMEM>>>();
    k_softmax<<<dim3(SQ, NHQ), 256>>>();
    k_pv<<<dim3(1, SQ / 128, NHQ), 256, GSMEM>>>();

    // Output projection
    k_out<<<dim3(HIDD / 128, SQ / 128), 256, GSMEM>>>(bo, out);

    (void)in_sizes; (void)n_in; (void)out_size;
}

// round 11
// speedup vs baseline: 3.3092x; 1.2435x over previous
#include <cuda_runtime.h>
#include <cstddef>
#include <cstdint>

#define SQ    2048
#define HIDD  2048
#define NHQ   16
#define NKVH  4
#define HDIM  128
#define QKVN  3072
#define QSCALE 0.08838834764831845f
#define RMSEPS 1e-6f

#define ATTN_N ((size_t)SQ * NHQ * HDIM)     // 4.19M elements

// ---------------------------------------------------------------------------
// Scratch (static device globals; allocation is forbidden)
// ---------------------------------------------------------------------------
__device__ float g_qkv   [(size_t)SQ * QKVN];
__device__ float g_q     [(size_t)SQ * NHQ * HDIM];     // tf32-rounded
__device__ float g_k     [(size_t)SQ * NKVH * HDIM];    // tf32-rounded
__device__ float g_vT    [(size_t)NKVH * HDIM * SQ];    // V^T, tf32-rounded
__device__ float g_scores[(size_t)NHQ * SQ * SQ];       // scores -> probs (tf32)
__device__ float g_attn  [ATTN_N];                      // tf32-rounded
__device__ float g_pvp   [4 * ATTN_N];                  // PV k-chunk partials
__device__ float g_hhi   [(size_t)SQ * HIDD];           // hidden, tf32-rounded
__device__ float g_whi   [(size_t)QKVN * HIDD];         // wqkv, tf32-rounded
__device__ float g_wot   [(size_t)HIDD * HIDD];         // wo tf32-rounded

// ---------------------------------------------------------------------------
// Helpers
// ---------------------------------------------------------------------------
__device__ __forceinline__ float tf32r(float x) {
    unsigned u;
    asm("cvt.rna.tf32.f32 %0, %1;" : "=r"(u) : "f"(x));
    return __uint_as_float(u);
}

__device__ __forceinline__ void cp16(uint32_t dst, const float* src) {
    asm volatile("cp.async.cg.shared.global [%0], [%1], 16;\n" :: "r"(dst), "l"(src));
}

__device__ __forceinline__ void ldm4(uint32_t* r, uint32_t addr) {
    asm volatile("ldmatrix.sync.aligned.m8n8.x4.shared.b16 {%0,%1,%2,%3}, [%4];\n"
                 : "=r"(r[0]), "=r"(r[1]), "=r"(r[2]), "=r"(r[3]) : "r"(addr));
}

__device__ __forceinline__ void mma8(float* c, const uint32_t* a,
                                     uint32_t b0, uint32_t b1) {
    asm volatile(
        "mma.sync.aligned.m16n8k8.row.col.f32.tf32.tf32.f32 "
        "{%0,%1,%2,%3}, {%4,%5,%6,%7}, {%8,%9}, {%0,%1,%2,%3};\n"
        : "+f"(c[0]), "+f"(c[1]), "+f"(c[2]), "+f"(c[3])
        : "r"(a[0]), "r"(a[1]), "r"(a[2]), "r"(a[3]), "r"(b0), "r"(b1));
}

#define SST    36                       // smem row stride (floats)
#define STAGEF (128 * SST)              // floats per matrix per stage
#define SSTB   (2 * STAGEF * 4)         // bytes per stage (A+B)
#define GSMEM  (3 * SSTB)               // 3 stages = 110592 B

// ---------------------------------------------------------------------------
// tf32 GEMM core: C = A * B^T (+bias)(tf32 out), 128x128x32 tiles,
// 3-stage cp.async, single barrier per k-tile.
// ---------------------------------------------------------------------------
__device__ __forceinline__ void cp_stage(const float* Ag, const float* Bg,
                                         int lda, int ldb,
                                         uint32_t dA, uint32_t dB) {
#pragma unroll
    for (int i = 0; i < 4; i++) {
        cp16(dA + i * 32 * SST * 4, Ag + (size_t)(i * 32) * lda);
        cp16(dB + i * 32 * SST * 4, Bg + (size_t)(i * 32) * ldb);
    }
}

__device__ __forceinline__ void gemm_core(
    const float* __restrict__ A, int lda,
    const float* __restrict__ B, int ldb,
    float* __restrict__ C, int ldc,
    int K, const float* __restrict__ bias,
    int cvt, int bx, int by)
{
    extern __shared__ float dsm[];
    const int tid  = threadIdx.x;
    const int wid  = tid >> 5, lane = tid & 31;
    const int wm   = (wid & 1) * 64, wn = (wid >> 1) * 32;
    const int ldrw = tid >> 3, ldcl = (tid & 7) * 4;

    const uint32_t sb = (uint32_t)__cvta_generic_to_shared(dsm);
    const float* Ag = A + (size_t)(by * 128 + ldrw) * lda + ldcl;
    const float* Bg = B + (size_t)(bx * 128 + ldrw) * ldb + ldcl;
    const uint32_t dA0 = sb + (ldrw * SST + ldcl) * 4;

    const int nK = K >> 5;

    float acc[4][4][4];
#pragma unroll
    for (int a = 0; a < 4; a++)
#pragma unroll
        for (int b = 0; b < 4; b++)
#pragma unroll
            for (int c = 0; c < 4; c++) acc[a][b][c] = 0.f;

    const int mi  = lane >> 3, l7 = lane & 7;
    const int aro = (mi & 1) * 8 + l7, aco = (mi >> 1) * 4;
    const int bro = (mi >> 1) * 8 + l7, bco = (mi & 1) * 4;

    cp_stage(Ag, Bg, lda, ldb, dA0, dA0 + STAGEF * 4);
    asm volatile("cp.async.commit_group;\n");
    if (nK > 1)
        cp_stage(Ag + 32, Bg + 32, lda, ldb, dA0 + SSTB, dA0 + SSTB + STAGEF * 4);
    asm volatile("cp.async.commit_group;\n");

    for (int kt = 0; kt < nK; kt++) {
        asm volatile("cp.async.wait_group 1;\n");
        __syncthreads();

        if (kt + 2 < nK) {
            const int sti = (kt + 2) % 3;
            cp_stage(Ag + (kt + 2) * 32, Bg + (kt + 2) * 32, lda, ldb,
                     dA0 + sti * SSTB, dA0 + sti * SSTB + STAGEF * 4);
        }
        asm volatile("cp.async.commit_group;\n");

        const uint32_t sA = sb + (kt % 3) * SSTB;
        const uint32_t sB = sA + STAGEF * 4;
#pragma unroll
        for (int k = 0; k < 32; k += 8) {
            uint32_t bq[8];
            ldm4(bq,     sB + ((wn +      bro) * SST + k + bco) * 4);
            ldm4(bq + 4, sB + ((wn + 16 + bro) * SST + k + bco) * 4);
#pragma unroll
            for (int mt = 0; mt < 4; mt++) {
                uint32_t aq[4];
                ldm4(aq, sA + ((wm + 16 * mt + aro) * SST + k + aco) * 4);
                mma8(acc[mt][0], aq, bq[0], bq[1]);
                mma8(acc[mt][1], aq, bq[2], bq[3]);
                mma8(acc[mt][2], aq, bq[4], bq[5]);
                mma8(acc[mt][3], aq, bq[6], bq[7]);
            }
        }
    }

    const int g = lane >> 2, tg = lane & 3;
#pragma unroll
    for (int mt = 0; mt < 4; mt++) {
#pragma unroll
        for (int nt = 0; nt < 4; nt++) {
            const int r0 = by * 128 + wm + 16 * mt + g;
            const int c0 = bx * 128 + wn + 8 * nt + tg * 2;
            float x0 = acc[mt][nt][0], x1 = acc[mt][nt][1];
            float x2 = acc[mt][nt][2], x3 = acc[mt][nt][3];
            if (bias) {
                float b0 = bias[c0], b1 = bias[c0 + 1];
                x0 += b0; x1 += b1; x2 += b0; x3 += b1;
            }
            if (cvt) { x0 = tf32r(x0); x1 = tf32r(x1); x2 = tf32r(x2); x3 = tf32r(x3); }
            *reinterpret_cast<float2*>(C + (size_t)r0 * ldc + c0) = make_float2(x0, x1);
            *reinterpret_cast<float2*>(C + (size_t)(r0 + 8) * ldc + c0) = make_float2(x2, x3);
        }
    }
}

// ---------------------------------------------------------------------------
// GEMM kernels
// ---------------------------------------------------------------------------
__global__ void __launch_bounds__(256, 2) k_qkv(const float* __restrict__ bias) {
    gemm_core(g_hhi, HIDD, g_whi, HIDD, g_qkv, QKVN, HIDD, bias, 0,
              blockIdx.x, blockIdx.y);
}
__global__ void __launch_bounds__(256, 2) k_scores() {
    const int bx = blockIdx.x, by = blockIdx.y, h = blockIdx.z;
    if (bx > by) return;  // entirely above causal diagonal
    gemm_core(g_q + h * HDIM, NHQ * HDIM,
              g_k + (h >> 2) * HDIM, NKVH * HDIM,
              g_scores + (size_t)h * SQ * SQ, SQ, HDIM, nullptr, 0, bx, by);
}
// PV split along K into 512-wide chunks -> fp32 partials in g_pvp
__global__ void __launch_bounds__(256, 2) k_pv() {
    const int x = blockIdx.x, by = blockIdx.y, h = blockIdx.z;
    const int kmax = (by + 1) * 128;     // p[s,t]=0 for t>s (tile-aligned)
    const int k0 = x * 512;
    if (k0 >= kmax) return;
    const int len = min(512, kmax - k0);
    gemm_core(g_scores + (size_t)h * SQ * SQ + k0, SQ,
              g_vT + (size_t)(h >> 2) * HDIM * SQ + k0, SQ,
              g_pvp + (size_t)x * ATTN_N + h * HDIM, NHQ * HDIM,
              len, nullptr, 0, 0, by);
}
// Sum the per-row chunk count and tf32-round into g_attn
__global__ void __launch_bounds__(256) k_pv_reduce() {
    size_t i = (size_t)blockIdx.x * 256 + threadIdx.x;
    if (i >= ATTN_N) return;
    const int s  = (int)(i >> 11);          // / (NHQ*HDIM)
    const int nc = (s >> 9) + 1;            // chunks covering this row
    float v = g_pvp[i];
    if (nc > 1) v += g_pvp[ATTN_N + i];
    if (nc > 2) v += g_pvp[2 * ATTN_N + i];
    if (nc > 3) v += g_pvp[3 * ATTN_N + i];
    g_attn[i] = tf32r(v);
}
__global__ void __launch_bounds__(256, 2) k_out(const float* __restrict__ bo,
                                                float* __restrict__ out) {
    gemm_core(g_attn, NHQ * HDIM, g_wot, HIDD, out, HIDD, HIDD, bo, 0,
              blockIdx.x, blockIdx.y);
}

// ---------------------------------------------------------------------------
// tf32 prep kernels
// ---------------------------------------------------------------------------
__global__ void __launch_bounds__(256) k_round_h(const float* __restrict__ x) {
    int i = blockIdx.x * 256 + threadIdx.x;
    if (i < SQ * HIDD) g_hhi[i] = tf32r(x[i]);
}
__global__ void __launch_bounds__(256) k_cvt_w(const float* __restrict__ x) {
    int i = blockIdx.x * 256 + threadIdx.x;
    if (i < QKVN * HIDD) g_whi[i] = tf32r(x[i]);
}
__global__ void __launch_bounds__(256) k_cvt_wo(const float* __restrict__ x) {
    int i = blockIdx.x * 256 + threadIdx.x;
    if (i < HIDD * HIDD) g_wot[i] = tf32r(x[i]);
}

// V transpose: g_vT[c][s] = tf32(g_qkv[s][2560 + c]),  c in [0, 512)
__global__ void __launch_bounds__(256) k_vT() {
    __shared__ float t[32][33];
    const int c0 = blockIdx.x * 32, s0 = blockIdx.y * 32;
    const int tx = threadIdx.x, ty = threadIdx.y;  // 32 x 8
#pragma unroll
    for (int j = 0; j < 32; j += 8)
        t[ty + j][tx] = g_qkv[(size_t)(s0 + ty + j) * QKVN
                              + (NHQ + NKVH) * HDIM + c0 + tx];
    __syncthreads();
#pragma unroll
    for (int j = 0; j < 32; j += 8)
        g_vT[(size_t)(c0 + ty + j) * SQ + s0 + tx] = tf32r(t[tx][ty + j]);
}

// ---------------------------------------------------------------------------
// RMSNorm + RoPE (+q scaling), outputs tf32-rounded. grid (S, 20), 128 thr.
// ---------------------------------------------------------------------------
__global__ void __launch_bounds__(128) k_norm_rope(
    const float* __restrict__ cosb, const float* __restrict__ sinb,
    const float* __restrict__ qw,   const float* __restrict__ kw)
{
    const int s  = blockIdx.x;
    const int hh = blockIdx.y;
    const int d  = threadIdx.x;
    const float* row = g_qkv + (size_t)s * QKVN;

    const bool isq = (hh < 16);
    const int off = isq ? hh * HDIM : NHQ * HDIM + (hh - 16) * HDIM;
    float x = row[off + d];

    float sq = x * x;
#pragma unroll
    for (int o = 16; o; o >>= 1) sq += __shfl_xor_sync(0xffffffffu, sq, o);
    __shared__ float ws[4];
    __shared__ float rinv;
    if ((d & 31) == 0) ws[d >> 5] = sq;
    __syncthreads();
    if (d == 0)
        rinv = rsqrtf((ws[0] + ws[1] + ws[2] + ws[3]) * (1.0f / 128.0f) + RMSEPS);
    __syncthreads();

    const float w = isq ? qw[d] : kw[d];
    float xn = x * rinv * w;

    __shared__ float xs[128];
    xs[d] = xn;
    __syncthreads();

    const int j = d & 63;
    const float c  = cosb[(size_t)s * 64 + j];
    const float sn = sinb[(size_t)s * 64 + j];
    float o;
    if (d < 64) o = xs[d] * c - xs[d + 64] * sn;
    else        o = xs[j] * sn + xs[j + 64] * c;

    if (isq)
        g_q[(size_t)s * (NHQ * HDIM) + hh * HDIM + d] = tf32r(o * QSCALE);
    else
        g_k[(size_t)s * (NKVH * HDIM) + (hh - 16) * HDIM + d] = tf32r(o);
}

// ---------------------------------------------------------------------------
// Online causal softmax: fused max+sum pass, then exp+normalize pass.
// Writes tf32 probs; zeros only to the 128-aligned tile edge.
// ---------------------------------------------------------------------------
__global__ void __launch_bounds__(256) k_softmax()
{
    const int s = blockIdx.x, h = blockIdx.y;
    float* row = g_scores + ((size_t)h * SQ + s) * SQ;
    const int n = s + 1;
    const int kmax = ((s >> 7) + 1) << 7;
    const int tid = threadIdx.x;
    const int lane = tid & 31, w = tid >> 5;

    float m = -3.4e38f, ssum = 0.f;
    for (int t = tid; t < n; t += 256) {
        float x = row[t];
        float nm = fmaxf(m, x);
        ssum = ssum * expf(m - nm) + expf(x - nm);
        m = nm;
    }
#pragma unroll
    for (int o = 16; o; o >>= 1) {
        float om = __shfl_xor_sync(0xffffffffu, m, o);
        float os = __shfl_xor_sync(0xffffffffu, ssum, o);
        float nm = fmaxf(m, om);
        ssum = ssum * expf(m - nm) + os * expf(om - nm);
        m = nm;
    }
    __shared__ float sm[8], ss[8];
    if (lane == 0) { sm[w] = m; ss[w] = ssum; }
    __syncthreads();
    float M = sm[0], S = ss[0];
#pragma unroll
    for (int i = 1; i < 8; i++) {
        float nm = fmaxf(M, sm[i]);
        S = S * expf(M - nm) + ss[i] * expf(sm[i] - nm);
        M = nm;
    }
    const float inv = 1.0f / S;

    for (int t = tid; t < kmax; t += 256)
        row[t] = (t < n) ? tf32r(expf(row[t] - M) * inv) : 0.f;
}

// ---------------------------------------------------------------------------
// Launch
// ---------------------------------------------------------------------------
extern "C" void kernel_launch(void* const* d_in, const int* in_sizes, int n_in,
                              void* d_out, int out_size)
{
    const float* hidden = (const float*)d_in[0];
    const float* cosb   = (const float*)d_in[1];
    const float* sinb   = (const float*)d_in[2];
    const float* wqkv   = (const float*)d_in[6];
    const float* bqkv   = (const float*)d_in[7];
    const float* wo     = (const float*)d_in[8];
    const float* bo     = (const float*)d_in[9];
    const float* qw     = (const float*)d_in[10];
    const float* kw     = (const float*)d_in[11];
    float* out = (float*)d_out;

    cudaFuncSetAttribute(k_qkv,    cudaFuncAttributeMaxDynamicSharedMemorySize, GSMEM);
    cudaFuncSetAttribute(k_scores, cudaFuncAttributeMaxDynamicSharedMemorySize, GSMEM);
    cudaFuncSetAttribute(k_pv,     cudaFuncAttributeMaxDynamicSharedMemorySize, GSMEM);
    cudaFuncSetAttribute(k_out,    cudaFuncAttributeMaxDynamicSharedMemorySize, GSMEM);

    // tf32 prep (single-rounded operands only)
    k_round_h<<<(SQ * HIDD + 255) / 256, 256>>>(hidden);
    k_cvt_w<<<(QKVN * HIDD + 255) / 256, 256>>>(wqkv);
    k_cvt_wo<<<(HIDD * HIDD + 255) / 256, 256>>>(wo);

    // QKV single-pass tf32 GEMM
    k_qkv<<<dim3(QKVN / 128, SQ / 128), 256, GSMEM>>>(bqkv);

    // RMSNorm + RoPE (+scale) -> tf32 q/k; V transposed -> tf32 vT
    k_norm_rope<<<dim3(SQ, NHQ + NKVH), 128>>>(cosb, sinb, qw, kw);
    k_vT<<<dim3(NKVH * HDIM / 32, SQ / 32), dim3(32, 8)>>>();

    // Scores (causal tile skip), online softmax
    k_scores<<<dim3(SQ / 128, SQ / 128, NHQ), 256, GSMEM>>>();
    k_softmax<<<dim3(SQ, NHQ), 256>>>();

    // PV: K-chunked partials (balanced) + reduce
    k_pv<<<dim3(4, SQ / 128, NHQ), 256, GSMEM>>>();
    k_pv_reduce<<<(int)((ATTN_N + 255) / 256), 256>>>();

    // Output projection
    k_out<<<dim3(HIDD / 128, SQ / 128), 256, GSMEM>>>(bo, out);

    (void)in_sizes; (void)n_in; (void)out_size;
}